// round 16
// baseline (speedup 1.0000x reference)
#include <cuda_runtime.h>
#include <cuda_fp16.h>
#include <cstdint>
#include <cstddef>

// Problem constants
#define B_   4
#define S_   2048
#define D_   1024
#define H_   16
#define DH_  64
#define BSZ  (B_*S_)          // 8192 rows

// ---------------------------------------------------------------------------
// Scratch (device globals: allocation-free per harness rules)
// ---------------------------------------------------------------------------
__device__ __half g_X [(size_t)BSZ*D_];
__device__ __half g_Wq[(size_t)D_*D_];
__device__ __half g_Wk[(size_t)D_*D_];
__device__ __half g_Wv[(size_t)D_*D_];
__device__ __half g_Wo[(size_t)D_*D_];
__device__ __half g_Q [(size_t)BSZ*D_];
__device__ __half g_K [(size_t)BSZ*D_];
__device__ __half g_V [(size_t)BSZ*D_];
__device__ __half g_C [(size_t)BSZ*D_];

// ---------------------------------------------------------------------------
// Helpers
// ---------------------------------------------------------------------------
__device__ __forceinline__ void mma16(float* c, const uint32_t* a, const uint32_t* b) {
    asm volatile(
        "mma.sync.aligned.m16n8k16.row.col.f32.f16.f16.f32 "
        "{%0,%1,%2,%3}, {%4,%5,%6,%7}, {%8,%9}, {%0,%1,%2,%3};"
        : "+f"(c[0]), "+f"(c[1]), "+f"(c[2]), "+f"(c[3])
        : "r"(a[0]), "r"(a[1]), "r"(a[2]), "r"(a[3]), "r"(b[0]), "r"(b[1]));
}

// fp16-accumulated variant: D/C are 2x .f16x2 regs
__device__ __forceinline__ void mma16h(uint32_t* c, const uint32_t* a, const uint32_t* b) {
    asm volatile(
        "mma.sync.aligned.m16n8k16.row.col.f16.f16.f16.f16 "
        "{%0,%1}, {%2,%3,%4,%5}, {%6,%7}, {%0,%1};"
        : "+r"(c[0]), "+r"(c[1])
        : "r"(a[0]), "r"(a[1]), "r"(a[2]), "r"(a[3]), "r"(b[0]), "r"(b[1]));
}

__device__ __forceinline__ uint32_t ex2h2(uint32_t x) {
    uint32_t r;
    asm("ex2.approx.f16x2 %0, %1;" : "=r"(r) : "r"(x));
    return r;
}
__device__ __forceinline__ uint32_t hmul2u(uint32_t a, uint32_t b) {
    uint32_t d;
    asm("mul.f16x2 %0, %1, %2;" : "=r"(d) : "r"(a), "r"(b));
    return d;
}
__device__ __forceinline__ uint32_t hadd2u(uint32_t a, uint32_t b) {
    uint32_t d;
    asm("add.f16x2 %0, %1, %2;" : "=r"(d) : "r"(a), "r"(b));
    return d;
}

__device__ __forceinline__ void ldsm4(uint32_t* r, uint32_t saddr) {
    asm volatile("ldmatrix.sync.aligned.m8n8.x4.shared.b16 {%0,%1,%2,%3}, [%4];"
                 : "=r"(r[0]), "=r"(r[1]), "=r"(r[2]), "=r"(r[3]) : "r"(saddr));
}
__device__ __forceinline__ void ldsm4t(uint32_t* r, uint32_t saddr) {
    asm volatile("ldmatrix.sync.aligned.m8n8.x4.trans.shared.b16 {%0,%1,%2,%3}, [%4];"
                 : "=r"(r[0]), "=r"(r[1]), "=r"(r[2]), "=r"(r[3]) : "r"(saddr));
}

__device__ __forceinline__ void cpa16(uint32_t saddr, const void* g) {
    asm volatile("cp.async.cg.shared.global [%0], [%1], 16;" :: "r"(saddr), "l"(g));
}
__device__ __forceinline__ void cpa_commit() {
    asm volatile("cp.async.commit_group;");
}
template<int N> __device__ __forceinline__ void cpa_wait() {
    asm volatile("cp.async.wait_group %0;" :: "n"(N));
}

// ---------------------------------------------------------------------------
// Pre-round fp32 -> fp16, vectorized
// ---------------------------------------------------------------------------
__global__ void round_h(const float* __restrict__ in, __half* __restrict__ out, int n4) {
    int i = blockIdx.x * blockDim.x + threadIdx.x;
    if (i < n4) {
        float4 v = ((const float4*)in)[i];
        __half2* o2 = (__half2*)out + i * 2;
        o2[0] = __floats2half2_rn(v.x, v.y);
        o2[1] = __floats2half2_rn(v.z, v.w);
    }
}

__global__ void round_w4(const float* __restrict__ w0, const float* __restrict__ w1,
                         const float* __restrict__ w2, const float* __restrict__ w3,
                         __half* __restrict__ o0, __half* __restrict__ o1,
                         __half* __restrict__ o2, __half* __restrict__ o3, int n4) {
    int z = blockIdx.y;
    const float* in  = (z == 0) ? w0 : (z == 1) ? w1 : (z == 2) ? w2 : w3;
    __half*      out = (z == 0) ? o0 : (z == 1) ? o1 : (z == 2) ? o2 : o3;
    int i = blockIdx.x * blockDim.x + threadIdx.x;
    if (i < n4) {
        float4 v = ((const float4*)in)[i];
        __half2* op = (__half2*)out + i * 2;
        op[0] = __floats2half2_rn(v.x, v.y);
        op[1] = __floats2half2_rn(v.z, v.w);
    }
}

// ---------------------------------------------------------------------------
// fp16 GEMM v2: 128x128 CTA tile, 4 warps (64x64), BK=64 halves ->
// 16 k-iterations (HALF the barriers/waits of BK=32), 3-stage cp.async ring
// (wait<1>, issue i+2 — the attention-proven pattern). Row pad 72 halves
// (144B) = conflict-free ldsm phases. smem 110592/CTA -> 2 CTAs/SM.
// ---------------------------------------------------------------------------
#define HBK   64
#define HPAD  72
#define HSTG  3
#define HTILEB (128*HPAD*2)                 // 18432 bytes per matrix tile
#define HSTGB  (2*HTILEB)                   // 36864 per stage (A+B)
#define GEMM_SMEM_BYTES (HSTG * HSTGB)      // 110592

template<bool OUT_HALF>
__device__ __forceinline__
void gemm_body(const __half* __restrict__ A, const __half* __restrict__ W,
               const float* __restrict__ bias, void* __restrict__ Cv,
               float alpha, int bx, int by) {
    extern __shared__ char gsm[];
    uint32_t sbase = (uint32_t)__cvta_generic_to_shared(gsm);
    const int K = D_, N = D_;

    int tid = threadIdx.x, warp = tid >> 5, lane = tid & 31;
    int g = lane >> 2, t = lane & 3;
    int wm = (warp & 1) * 64;
    int wn = (warp >> 1) * 64;

    const __half* Ab = A + (size_t)bx * 128 * K;
    const __half* Wb = W + (size_t)by * 128 * K;

    // tile = 128 rows x 64 halves = 128 rows x 8 chunks of 16B = 1024 chunks
    auto issue = [&](int kt, int st) {
        uint32_t stb = sbase + st * HSTGB;
        int k0 = kt * HBK;
#pragma unroll
        for (int j = 0; j < 8; j++) {
            int ch  = tid + 128 * j;       // 0..1023
            int row = ch >> 3;             // 0..127
            int c8  = (ch & 7) * 8;        // half col 0..56
            uint32_t soff = (row * HPAD + c8) * 2;
            cpa16(stb + soff,          Ab + (size_t)row * K + k0 + c8);
            cpa16(stb + HTILEB + soff, Wb + (size_t)row * K + k0 + c8);
        }
    };

    int rowA = wm + (lane & 15);
    int colA = (lane >> 4) * 8;
    int rowB = wn + (lane & 7) + (lane >> 4) * 8;
    int colB = ((lane >> 3) & 1) * 8;
    uint32_t aOff = (rowA * HPAD + colA) * 2;
    uint32_t bOff = (rowB * HPAD + colB) * 2 + HTILEB;

    float acc[4][8][4];
#pragma unroll
    for (int i = 0; i < 4; i++)
#pragma unroll
        for (int j = 0; j < 8; j++)
#pragma unroll
            for (int r = 0; r < 4; r++) acc[i][j][r] = 0.f;

    issue(0, 0); cpa_commit();
    issue(1, 1); cpa_commit();

    const int NT = K / HBK;     // 16
    for (int kt = 0; kt < NT; kt++) {
        cpa_wait<1>();          // tile kt resident
        __syncthreads();
        if (kt + 2 < NT) issue(kt + 2, (kt + 2) % HSTG);
        cpa_commit();

        uint32_t stb = sbase + (kt % HSTG) * HSTGB;
#pragma unroll
        for (int kk = 0; kk < 4; kk++) {
            int kb = kk * 16;   // halves
            uint32_t af[4][4], bf[8][2];
#pragma unroll
            for (int mt = 0; mt < 4; mt++)
                ldsm4(af[mt], stb + aOff + (mt * 16 * HPAD + kb) * 2);
#pragma unroll
            for (int ntp = 0; ntp < 4; ntp++) {
                uint32_t r[4];
                ldsm4(r, stb + bOff + (ntp * 16 * HPAD + kb) * 2);
                bf[2*ntp][0]   = r[0]; bf[2*ntp][1]   = r[1];
                bf[2*ntp+1][0] = r[2]; bf[2*ntp+1][1] = r[3];
            }
#pragma unroll
            for (int mt = 0; mt < 4; mt++)
#pragma unroll
                for (int nt = 0; nt < 8; nt++)
                    mma16(acc[mt][nt], af[mt], bf[nt]);
        }
        // no trailing barrier: next iteration's top barrier precedes the
        // overwrite of stage (kt+2)%3, which was last read in iter kt-1.
    }

    size_t mbase = (size_t)bx * 128;
    int    nbase = by * 128;
#pragma unroll
    for (int mt = 0; mt < 4; mt++) {
#pragma unroll
        for (int nt = 0; nt < 8; nt++) {
            int n0 = nbase + wn + nt * 8 + 2 * t;
            float b0 = bias[n0], b1 = bias[n0 + 1];
            size_t r0 = mbase + wm + mt * 16 + g;
            float v00 = (acc[mt][nt][0] + b0) * alpha;
            float v01 = (acc[mt][nt][1] + b1) * alpha;
            float v10 = (acc[mt][nt][2] + b0) * alpha;
            float v11 = (acc[mt][nt][3] + b1) * alpha;
            if (OUT_HALF) {
                __half* C = (__half*)Cv;
                *(__half2*)(C + r0 * N + n0)       = __floats2half2_rn(v00, v01);
                *(__half2*)(C + (r0 + 8) * N + n0) = __floats2half2_rn(v10, v11);
            } else {
                float* C = (float*)Cv;
                *(float2*)(C + r0 * N + n0)       = make_float2(v00, v01);
                *(float2*)(C + (r0 + 8) * N + n0) = make_float2(v10, v11);
            }
        }
    }
}

__global__ __launch_bounds__(128, 2)
void gemm_qkv(const __half* __restrict__ A,
              const __half* __restrict__ W0, const __half* __restrict__ W1,
              const __half* __restrict__ W2,
              const float* __restrict__ b0, const float* __restrict__ b1,
              const float* __restrict__ b2,
              __half* __restrict__ C0, __half* __restrict__ C1,
              __half* __restrict__ C2) {
    int z = blockIdx.z;
    const __half* W = (z == 0) ? W0 : (z == 1) ? W1 : W2;
    const float*  b = (z == 0) ? b0 : (z == 1) ? b1 : b2;
    __half*       C = (z == 0) ? C0 : (z == 1) ? C1 : C2;
    // Q projection scale: 1/sqrt(64) * log2(e), so softmax uses exp2 directly
    float alpha = (z == 0) ? 0.125f * 1.44269504f : 1.0f;
    gemm_body<true>(A, W, b, C, alpha, blockIdx.x, blockIdx.y);
}

__global__ __launch_bounds__(128, 2)
void gemm_o(const __half* __restrict__ A, const __half* __restrict__ W,
            const float* __restrict__ bias, float* __restrict__ C) {
    gemm_body<false>(A, W, bias, C, 1.0f, blockIdx.x, blockIdx.y);
}

// ---------------------------------------------------------------------------
// Flash attention v7 (unchanged from R15, the measured best):
//  - 128-row CTA, 8 warps x 16 rows, 2 CTAs/SM (regs <= 128)
//  - fp16-accum QK, ex2h2+hmul2 softmax
//  - row sums via add.f16x2 trees (idle fma/alu pipes)
// ---------------------------------------------------------------------------
#define QP 72                              // halves per row
#define QROWB (QP*2)                       // 144 bytes
#define AOF_Q 0
#define AQSZ  (128*QROWB)                  // 18432
#define AOF_K AQSZ                         // 18432
#define AKSZ  (128*QROWB)                  // 18432
#define AOF_V (AOF_K + 2*AKSZ)             // 55296
#define AOF_MH (AOF_V + 2*AKSZ)            // 92160 (half mask table)
#define ATTN_SMEM_BYTES (AOF_MH + S_*2)    // 96256
#define ATHREADS 256

__global__ __launch_bounds__(ATHREADS, 2)
void attn_kernel(const __half* __restrict__ Q, const __half* __restrict__ K,
                 const __half* __restrict__ V, const int* __restrict__ mask,
                 __half* __restrict__ ctx) {
    extern __shared__ char smc[];
    uint32_t sbase = (uint32_t)__cvta_generic_to_shared(smc);

    int tid  = threadIdx.x;
    int warp = tid >> 5, lane = tid & 31;
    int g = lane >> 2, t = lane & 3;
    int q0 = blockIdx.x * 128;
    int b  = blockIdx.y >> 4;
    int h  = blockIdx.y & 15;
    const size_t headoff = (size_t)h * DH_;
    const size_t brow    = (size_t)b * S_;

    auto issueKV = [&](int i) {
        int buf = i & 1;
#pragma unroll
        for (int j = 0; j < 4; j++) {
            int ch  = tid + ATHREADS * j;  // 0..1023
            int row = ch >> 3;             // 0..127
            int c8  = (ch & 7) * 8;
            size_t gaddr = (brow + (size_t)i * 128 + row) * D_ + headoff + c8;
            uint32_t soff = row * QROWB + c8 * 2;
            cpa16(sbase + AOF_K + buf * AKSZ + soff, K + gaddr);
            cpa16(sbase + AOF_V + buf * AKSZ + soff, V + gaddr);
        }
    };

    // prologue: Q tile (128 rows x 8 chunks = 1024 chunks)
#pragma unroll
    for (int j = 0; j < 4; j++) {
        int ch  = tid + ATHREADS * j;
        int row = ch >> 3;
        int c8  = (ch & 7) * 8;
        cpa16(sbase + AOF_Q + row * QROWB + c8 * 2,
              Q + (brow + q0 + row) * D_ + headoff + c8);
    }
    // mask as 0/1 half table (8 cols per thread, 256 threads -> 2048 cols)
    {
        int c0 = tid * 8;
        uint32_t hw[4];
#pragma unroll
        for (int j = 0; j < 4; j++) {
            int2 mv = *(const int2*)&mask[b * S_ + c0 + 2 * j];
            uint32_t lo = mv.x ? 0x3C00u : 0u;
            uint32_t hi = mv.y ? 0x3C00u : 0u;
            hw[j] = lo | (hi << 16);
        }
        *(uint4*)(smc + AOF_MH + c0 * 2) = make_uint4(hw[0], hw[1], hw[2], hw[3]);
    }
    issueKV(0);
    cpa_commit();
    issueKV(1);
    cpa_commit();

    const int wm = warp * 16;              // 8 warps x 16 rows (1 m-tile)

    int rowQ = wm + (lane & 15);
    int colQ = (lane >> 4) * 8;
    int rowK = (lane & 7) + (lane >> 4) * 8;
    int colK = ((lane >> 3) & 1) * 8;
    int rowV = (lane & 7) + ((lane >> 3) & 1) * 8;
    int colV = (lane >> 4) * 8;
    uint32_t qBase = sbase + AOF_Q + (rowQ * QP + colQ) * 2;
    uint32_t kOff  = (rowK * QP + colK) * 2;
    uint32_t vOff  = (rowV * QP + colV) * 2;

    float o[8][4];
#pragma unroll
    for (int nt = 0; nt < 8; nt++)
#pragma unroll
        for (int r = 0; r < 4; r++) o[nt][r] = 0.f;
    float ls0 = 0.f, ls1 = 0.f;           // fp32 row-sum accumulators

    for (int i = 0; i < 16; i++) {
        cpa_wait<1>();
        __syncthreads();
        uint32_t kBase = sbase + AOF_K + (i & 1) * AKSZ + kOff;
        uint32_t vBase = sbase + AOF_V + (i & 1) * AKSZ;

        // ---- S = Q K^T, fp16 accumulate (Q carries log2e/8) ----
        uint32_t sch[16][2];
#pragma unroll
        for (int nt = 0; nt < 16; nt++) { sch[nt][0] = 0u; sch[nt][1] = 0u; }

#pragma unroll
        for (int kk = 0; kk < 4; kk++) {
            int kb = kk * 16;
            uint32_t af[4];
            ldsm4(af, qBase + kb * 2);
#pragma unroll
            for (int ntp = 0; ntp < 8; ntp++) {
                uint32_t r[4];
                ldsm4(r, kBase + (ntp * 16 * QP + kb) * 2);
                uint32_t bf0[2] = {r[0], r[1]};
                uint32_t bf1[2] = {r[2], r[3]};
                mma16h(sch[2*ntp],   af, bf0);
                mma16h(sch[2*ntp+1], af, bf1);
            }
        }

        // ---- p = exp2(s) * mask : 32 ex2h2 + 32 hmul2, in place ----
        int colbase = i * 128;
#pragma unroll
        for (int nt = 0; nt < 16; nt++) {
            uint32_t m2 = *(const uint32_t*)(smc + AOF_MH + (colbase + nt * 8 + 2 * t) * 2);
            sch[nt][0] = hmul2u(ex2h2(sch[nt][0]), m2);
            sch[nt][1] = hmul2u(ex2h2(sch[nt][1]), m2);
        }

        // ---- row sums via hadd2 trees (fma/alu pipes; tensor untouched) ----
        {
            uint32_t a0 = hadd2u(sch[0][0], sch[1][0]);
            uint32_t a1 = hadd2u(sch[2][0], sch[3][0]);
            uint32_t a2 = hadd2u(sch[4][0], sch[5][0]);
            uint32_t a3 = hadd2u(sch[6][0], sch[7][0]);
            uint32_t a4 = hadd2u(sch[8][0], sch[9][0]);
            uint32_t a5 = hadd2u(sch[10][0], sch[11][0]);
            uint32_t a6 = hadd2u(sch[12][0], sch[13][0]);
            uint32_t a7 = hadd2u(sch[14][0], sch[15][0]);
            a0 = hadd2u(a0, a1); a2 = hadd2u(a2, a3);
            a4 = hadd2u(a4, a5); a6 = hadd2u(a6, a7);
            a0 = hadd2u(a0, a2); a4 = hadd2u(a4, a6);
            a0 = hadd2u(a0, a4);
            float2 f0 = __half22float2(*(__half2*)&a0);
            ls0 += f0.x + f0.y;

            uint32_t b0 = hadd2u(sch[0][1], sch[1][1]);
            uint32_t b1 = hadd2u(sch[2][1], sch[3][1]);
            uint32_t b2 = hadd2u(sch[4][1], sch[5][1]);
            uint32_t b3 = hadd2u(sch[6][1], sch[7][1]);
            uint32_t b4 = hadd2u(sch[8][1], sch[9][1]);
            uint32_t b5 = hadd2u(sch[10][1], sch[11][1]);
            uint32_t b6 = hadd2u(sch[12][1], sch[13][1]);
            uint32_t b7 = hadd2u(sch[14][1], sch[15][1]);
            b0 = hadd2u(b0, b1); b2 = hadd2u(b2, b3);
            b4 = hadd2u(b4, b5); b6 = hadd2u(b6, b7);
            b0 = hadd2u(b0, b2); b4 = hadd2u(b4, b6);
            b0 = hadd2u(b0, b4);
            float2 f1 = __half22float2(*(__half2*)&b0);
            ls1 += f1.x + f1.y;
        }

        // ---- O += P @ V : P A-frags ARE the sch registers ----
#pragma unroll
        for (int kk = 0; kk < 8; kk++) {
            uint32_t af[4];
            af[0] = sch[2*kk  ][0];
            af[1] = sch[2*kk  ][1];
            af[2] = sch[2*kk+1][0];
            af[3] = sch[2*kk+1][1];
            uint32_t vk = vBase + kk * 16 * QROWB;
#pragma unroll
            for (int ntv = 0; ntv < 4; ntv++) {
                uint32_t r[4];
                ldsm4t(r, vk + vOff + ntv * 16 * 2);
                uint32_t bf0[2] = {r[0], r[1]};
                uint32_t bf1[2] = {r[2], r[3]};
                mma16(o[2*ntv],   af, bf0);
                mma16(o[2*ntv+1], af, bf1);
            }
        }

        __syncthreads();
        if (i + 2 < 16) issueKV(i + 2);
        cpa_commit();
    }

    // ---- epilogue: quad-reduce row sums, normalize, store half2 ----
    ls0 += __shfl_xor_sync(0xffffffffu, ls0, 1);
    ls0 += __shfl_xor_sync(0xffffffffu, ls0, 2);
    ls1 += __shfl_xor_sync(0xffffffffu, ls1, 1);
    ls1 += __shfl_xor_sync(0xffffffffu, ls1, 2);
    float i0 = 1.f / ls0, i1 = 1.f / ls1;
    size_t r0 = brow + q0 + wm + g;
#pragma unroll
    for (int nt = 0; nt < 8; nt++) {
        int c = nt * 8 + 2 * t;
        *(__half2*)(ctx + r0 * D_ + headoff + c) =
            __floats2half2_rn(o[nt][0] * i0, o[nt][1] * i0);
        *(__half2*)(ctx + (r0 + 8) * D_ + headoff + c) =
            __floats2half2_rn(o[nt][2] * i1, o[nt][3] * i1);
    }
}

// ---------------------------------------------------------------------------
// Launch
// ---------------------------------------------------------------------------
extern "C" void kernel_launch(void* const* d_in, const int* in_sizes, int n_in,
                              void* d_out, int out_size) {
    const float* x    = (const float*)d_in[0];
    const int*   mask = (const int*)  d_in[1];
    const float* Wq   = (const float*)d_in[2];
    const float* bq   = (const float*)d_in[3];
    const float* Wk   = (const float*)d_in[4];
    const float* bk   = (const float*)d_in[5];
    const float* Wv   = (const float*)d_in[6];
    const float* bv   = (const float*)d_in[7];
    const float* Wo   = (const float*)d_in[8];
    const float* bo   = (const float*)d_in[9];
    float* out = (float*)d_out;

    __half *xr, *wq, *wk, *wv, *wo, *q, *k, *v, *c;
    cudaGetSymbolAddress((void**)&xr, g_X);
    cudaGetSymbolAddress((void**)&wq, g_Wq);
    cudaGetSymbolAddress((void**)&wk, g_Wk);
    cudaGetSymbolAddress((void**)&wv, g_Wv);
    cudaGetSymbolAddress((void**)&wo, g_Wo);
    cudaGetSymbolAddress((void**)&q,  g_Q);
    cudaGetSymbolAddress((void**)&k,  g_K);
    cudaGetSymbolAddress((void**)&v,  g_V);
    cudaGetSymbolAddress((void**)&c,  g_C);

    cudaFuncSetAttribute(gemm_qkv,
                         cudaFuncAttributeMaxDynamicSharedMemorySize, GEMM_SMEM_BYTES);
    cudaFuncSetAttribute(gemm_o,
                         cudaFuncAttributeMaxDynamicSharedMemorySize, GEMM_SMEM_BYTES);
    cudaFuncSetAttribute(attn_kernel,
                         cudaFuncAttributeMaxDynamicSharedMemorySize, ATTN_SMEM_BYTES);

    // 1) pre-round GEMM operands to fp16
    int nx4 = BSZ * D_ / 4;
    int nw4 = D_ * D_ / 4;
    round_h<<<nx4 / 256, 256>>>(x, xr, nx4);
    round_w4<<<dim3(nw4 / 256, 4), 256>>>(Wq, Wk, Wv, Wo, wq, wk, wv, wo, nw4);

    // 2) fused QKV projections (fp16 out; Q pre-scaled by log2e/8)
    dim3 gqkv(BSZ / 128, D_ / 128, 3);
    gemm_qkv<<<gqkv, 128, GEMM_SMEM_BYTES>>>(xr, wq, wk, wv, bq, bk, bv, q, k, v);

    // 3) attention (128-row CTAs, 256 threads, 2 CTAs/SM)
    attn_kernel<<<dim3(S_ / 128, B_ * H_), ATHREADS, ATTN_SMEM_BYTES>>>(q, k, v, mask, c);

    // 4) output projection (fp32 out)
    dim3 go(BSZ / 128, D_ / 128);
    gemm_o<<<go, 128, GEMM_SMEM_BYTES>>>(c, wo, bo, out);
}

// round 17
// speedup vs baseline: 1.0285x; 1.0285x over previous
#include <cuda_runtime.h>
#include <cuda_fp16.h>
#include <cstdint>
#include <cstddef>

// Problem constants
#define B_   4
#define S_   2048
#define D_   1024
#define H_   16
#define DH_  64
#define BSZ  (B_*S_)          // 8192 rows

// ---------------------------------------------------------------------------
// Scratch (device globals: allocation-free per harness rules)
// ---------------------------------------------------------------------------
__device__ __half g_X [(size_t)BSZ*D_];
__device__ __half g_Wq[(size_t)D_*D_];
__device__ __half g_Wk[(size_t)D_*D_];
__device__ __half g_Wv[(size_t)D_*D_];
__device__ __half g_Wo[(size_t)D_*D_];
__device__ __half g_Q [(size_t)BSZ*D_];
__device__ __half g_K [(size_t)BSZ*D_];
__device__ __half g_V [(size_t)BSZ*D_];
__device__ __half g_C [(size_t)BSZ*D_];

// ---------------------------------------------------------------------------
// Helpers
// ---------------------------------------------------------------------------
__device__ __forceinline__ void mma16(float* c, const uint32_t* a, const uint32_t* b) {
    asm volatile(
        "mma.sync.aligned.m16n8k16.row.col.f32.f16.f16.f32 "
        "{%0,%1,%2,%3}, {%4,%5,%6,%7}, {%8,%9}, {%0,%1,%2,%3};"
        : "+f"(c[0]), "+f"(c[1]), "+f"(c[2]), "+f"(c[3])
        : "r"(a[0]), "r"(a[1]), "r"(a[2]), "r"(a[3]), "r"(b[0]), "r"(b[1]));
}

// fp16-accumulated variant: D/C are 2x .f16x2 regs
__device__ __forceinline__ void mma16h(uint32_t* c, const uint32_t* a, const uint32_t* b) {
    asm volatile(
        "mma.sync.aligned.m16n8k16.row.col.f16.f16.f16.f16 "
        "{%0,%1}, {%2,%3,%4,%5}, {%6,%7}, {%0,%1};"
        : "+r"(c[0]), "+r"(c[1])
        : "r"(a[0]), "r"(a[1]), "r"(a[2]), "r"(a[3]), "r"(b[0]), "r"(b[1]));
}

__device__ __forceinline__ uint32_t ex2h2(uint32_t x) {
    uint32_t r;
    asm("ex2.approx.f16x2 %0, %1;" : "=r"(r) : "r"(x));
    return r;
}
__device__ __forceinline__ uint32_t hmul2u(uint32_t a, uint32_t b) {
    uint32_t d;
    asm("mul.f16x2 %0, %1, %2;" : "=r"(d) : "r"(a), "r"(b));
    return d;
}
__device__ __forceinline__ uint32_t hadd2u(uint32_t a, uint32_t b) {
    uint32_t d;
    asm("add.f16x2 %0, %1, %2;" : "=r"(d) : "r"(a), "r"(b));
    return d;
}

__device__ __forceinline__ void ldsm4(uint32_t* r, uint32_t saddr) {
    asm volatile("ldmatrix.sync.aligned.m8n8.x4.shared.b16 {%0,%1,%2,%3}, [%4];"
                 : "=r"(r[0]), "=r"(r[1]), "=r"(r[2]), "=r"(r[3]) : "r"(saddr));
}
__device__ __forceinline__ void ldsm4t(uint32_t* r, uint32_t saddr) {
    asm volatile("ldmatrix.sync.aligned.m8n8.x4.trans.shared.b16 {%0,%1,%2,%3}, [%4];"
                 : "=r"(r[0]), "=r"(r[1]), "=r"(r[2]), "=r"(r[3]) : "r"(saddr));
}

__device__ __forceinline__ void cpa16(uint32_t saddr, const void* g) {
    asm volatile("cp.async.cg.shared.global [%0], [%1], 16;" :: "r"(saddr), "l"(g));
}
__device__ __forceinline__ void cpa_commit() {
    asm volatile("cp.async.commit_group;");
}
template<int N> __device__ __forceinline__ void cpa_wait() {
    asm volatile("cp.async.wait_group %0;" :: "n"(N));
}

// ---------------------------------------------------------------------------
// Pre-round fp32 -> fp16: ONE launch for x and all four weight matrices.
// grid = (nw4/256, 5); y==4 -> x (8 strided float4 per thread), y<4 -> W[y].
// ---------------------------------------------------------------------------
__global__ void round_all(const float* __restrict__ x,
                          const float* __restrict__ w0, const float* __restrict__ w1,
                          const float* __restrict__ w2, const float* __restrict__ w3,
                          __half* __restrict__ xo,
                          __half* __restrict__ o0, __half* __restrict__ o1,
                          __half* __restrict__ o2, __half* __restrict__ o3,
                          int nw4) {
    int z = blockIdx.y;
    if (z == 4) {
        // x: 8 chunks per thread, stride = gridDim.x * blockDim.x
        int stride = gridDim.x * blockDim.x;          // nw4
        int i0 = blockIdx.x * blockDim.x + threadIdx.x;
#pragma unroll
        for (int j = 0; j < 8; j++) {
            int i = i0 + j * stride;
            float4 v = ((const float4*)x)[i];
            __half2* o2p = (__half2*)xo + i * 2;
            o2p[0] = __floats2half2_rn(v.x, v.y);
            o2p[1] = __floats2half2_rn(v.z, v.w);
        }
        return;
    }
    const float* in  = (z == 0) ? w0 : (z == 1) ? w1 : (z == 2) ? w2 : w3;
    __half*      out = (z == 0) ? o0 : (z == 1) ? o1 : (z == 2) ? o2 : o3;
    int i = blockIdx.x * blockDim.x + threadIdx.x;
    if (i < nw4) {
        float4 v = ((const float4*)in)[i];
        __half2* op = (__half2*)out + i * 2;
        op[0] = __floats2half2_rn(v.x, v.y);
        op[1] = __floats2half2_rn(v.z, v.w);
    }
}

// ---------------------------------------------------------------------------
// fp16 GEMM (R15 measured-best): 128x128 CTA tile, 4 warps (64x64 warp tiles),
// BK=32 halves, 4-stage cp.async (wait<2>, issue kt+3), row pad 40 halves.
// ---------------------------------------------------------------------------
#define HBK   32
#define HPAD  40
#define HSTG  4
#define HTILEB (128*HPAD*2)                 // 10240 bytes per tile
#define HSTGB  (2*HTILEB)                   // 20480 per stage (A+B)
#define GEMM_SMEM_BYTES (HSTG * HSTGB)      // 81920

template<bool OUT_HALF>
__device__ __forceinline__
void gemm_body(const __half* __restrict__ A, const __half* __restrict__ W,
               const float* __restrict__ bias, void* __restrict__ Cv,
               float alpha, int bx, int by) {
    extern __shared__ char gsm[];
    uint32_t sbase = (uint32_t)__cvta_generic_to_shared(gsm);
    const int K = D_, N = D_;

    int tid = threadIdx.x, warp = tid >> 5, lane = tid & 31;
    int g = lane >> 2, t = lane & 3;
    int wm = (warp & 1) * 64;
    int wn = (warp >> 1) * 64;

    const __half* Ab = A + (size_t)bx * 128 * K;
    const __half* Wb = W + (size_t)by * 128 * K;

    int lr  = tid >> 2;
    int lc8 = (tid & 3) * 8;

    auto issue = [&](int kt) {
        uint32_t stb = sbase + (kt & (HSTG - 1)) * HSTGB;
        int k0 = kt * HBK;
#pragma unroll
        for (int j = 0; j < 4; j++) {
            int row = lr + j * 32;
            uint32_t soff = (row * HPAD + lc8) * 2;
            cpa16(stb + soff,          Ab + (size_t)row * K + k0 + lc8);
            cpa16(stb + HTILEB + soff, Wb + (size_t)row * K + k0 + lc8);
        }
    };

    int rowA = wm + (lane & 15);
    int colA = (lane >> 4) * 8;
    int rowB = wn + (lane & 7) + (lane >> 4) * 8;
    int colB = ((lane >> 3) & 1) * 8;
    uint32_t aOff = (rowA * HPAD + colA) * 2;
    uint32_t bOff = (rowB * HPAD + colB) * 2 + HTILEB;

    float acc[4][8][4];
#pragma unroll
    for (int i = 0; i < 4; i++)
#pragma unroll
        for (int j = 0; j < 8; j++)
#pragma unroll
            for (int r = 0; r < 4; r++) acc[i][j][r] = 0.f;

    issue(0); cpa_commit();
    issue(1); cpa_commit();
    issue(2); cpa_commit();

    const int NT = K / HBK;
    for (int kt = 0; kt < NT; kt++) {
        cpa_wait<2>();
        __syncthreads();
        if (kt + 3 < NT) issue(kt + 3);
        cpa_commit();

        uint32_t stb = sbase + (kt & (HSTG - 1)) * HSTGB;
#pragma unroll
        for (int kk = 0; kk < 2; kk++) {
            int kb = kk * 16;
            uint32_t af[4][4], bf[8][2];
#pragma unroll
            for (int mt = 0; mt < 4; mt++)
                ldsm4(af[mt], stb + aOff + (mt * 16 * HPAD + kb) * 2);
#pragma unroll
            for (int ntp = 0; ntp < 4; ntp++) {
                uint32_t r[4];
                ldsm4(r, stb + bOff + (ntp * 16 * HPAD + kb) * 2);
                bf[2*ntp][0]   = r[0]; bf[2*ntp][1]   = r[1];
                bf[2*ntp+1][0] = r[2]; bf[2*ntp+1][1] = r[3];
            }
#pragma unroll
            for (int mt = 0; mt < 4; mt++)
#pragma unroll
                for (int nt = 0; nt < 8; nt++)
                    mma16(acc[mt][nt], af[mt], bf[nt]);
        }
    }

    size_t mbase = (size_t)bx * 128;
    int    nbase = by * 128;
#pragma unroll
    for (int mt = 0; mt < 4; mt++) {
#pragma unroll
        for (int nt = 0; nt < 8; nt++) {
            int n0 = nbase + wn + nt * 8 + 2 * t;
            float b0 = bias[n0], b1 = bias[n0 + 1];
            size_t r0 = mbase + wm + mt * 16 + g;
            float v00 = (acc[mt][nt][0] + b0) * alpha;
            float v01 = (acc[mt][nt][1] + b1) * alpha;
            float v10 = (acc[mt][nt][2] + b0) * alpha;
            float v11 = (acc[mt][nt][3] + b1) * alpha;
            if (OUT_HALF) {
                __half* C = (__half*)Cv;
                *(__half2*)(C + r0 * N + n0)       = __floats2half2_rn(v00, v01);
                *(__half2*)(C + (r0 + 8) * N + n0) = __floats2half2_rn(v10, v11);
            } else {
                float* C = (float*)Cv;
                *(float2*)(C + r0 * N + n0)       = make_float2(v00, v01);
                *(float2*)(C + (r0 + 8) * N + n0) = make_float2(v10, v11);
            }
        }
    }
}

__global__ __launch_bounds__(128, 2)
void gemm_qkv(const __half* __restrict__ A,
              const __half* __restrict__ W0, const __half* __restrict__ W1,
              const __half* __restrict__ W2,
              const float* __restrict__ b0, const float* __restrict__ b1,
              const float* __restrict__ b2,
              __half* __restrict__ C0, __half* __restrict__ C1,
              __half* __restrict__ C2) {
    int z = blockIdx.z;
    const __half* W = (z == 0) ? W0 : (z == 1) ? W1 : W2;
    const float*  b = (z == 0) ? b0 : (z == 1) ? b1 : b2;
    __half*       C = (z == 0) ? C0 : (z == 1) ? C1 : C2;
    // Q projection scale: 1/sqrt(64) * log2(e), so softmax uses exp2 directly
    float alpha = (z == 0) ? 0.125f * 1.44269504f : 1.0f;
    gemm_body<true>(A, W, b, C, alpha, blockIdx.x, blockIdx.y);
}

__global__ __launch_bounds__(128, 2)
void gemm_o(const __half* __restrict__ A, const __half* __restrict__ W,
            const float* __restrict__ bias, float* __restrict__ C) {
    gemm_body<false>(A, W, bias, C, 1.0f, blockIdx.x, blockIdx.y);
}

// ---------------------------------------------------------------------------
// Flash attention v7 (R15 measured-best, unchanged):
//  - 128-row CTA, 8 warps x 16 rows, 2 CTAs/SM (regs <= 128)
//  - fp16-accum QK, ex2h2+hmul2 softmax
//  - row sums via add.f16x2 trees (idle fma/alu pipes)
// ---------------------------------------------------------------------------
#define QP 72                              // halves per row
#define QROWB (QP*2)                       // 144 bytes
#define AOF_Q 0
#define AQSZ  (128*QROWB)                  // 18432
#define AOF_K AQSZ                         // 18432
#define AKSZ  (128*QROWB)                  // 18432
#define AOF_V (AOF_K + 2*AKSZ)             // 55296
#define AOF_MH (AOF_V + 2*AKSZ)            // 92160 (half mask table)
#define ATTN_SMEM_BYTES (AOF_MH + S_*2)    // 96256
#define ATHREADS 256

__global__ __launch_bounds__(ATHREADS, 2)
void attn_kernel(const __half* __restrict__ Q, const __half* __restrict__ K,
                 const __half* __restrict__ V, const int* __restrict__ mask,
                 __half* __restrict__ ctx) {
    extern __shared__ char smc[];
    uint32_t sbase = (uint32_t)__cvta_generic_to_shared(smc);

    int tid  = threadIdx.x;
    int warp = tid >> 5, lane = tid & 31;
    int g = lane >> 2, t = lane & 3;
    int q0 = blockIdx.x * 128;
    int b  = blockIdx.y >> 4;
    int h  = blockIdx.y & 15;
    const size_t headoff = (size_t)h * DH_;
    const size_t brow    = (size_t)b * S_;

    auto issueKV = [&](int i) {
        int buf = i & 1;
#pragma unroll
        for (int j = 0; j < 4; j++) {
            int ch  = tid + ATHREADS * j;  // 0..1023
            int row = ch >> 3;             // 0..127
            int c8  = (ch & 7) * 8;
            size_t gaddr = (brow + (size_t)i * 128 + row) * D_ + headoff + c8;
            uint32_t soff = row * QROWB + c8 * 2;
            cpa16(sbase + AOF_K + buf * AKSZ + soff, K + gaddr);
            cpa16(sbase + AOF_V + buf * AKSZ + soff, V + gaddr);
        }
    };

    // prologue: Q tile (128 rows x 8 chunks = 1024 chunks)
#pragma unroll
    for (int j = 0; j < 4; j++) {
        int ch  = tid + ATHREADS * j;
        int row = ch >> 3;
        int c8  = (ch & 7) * 8;
        cpa16(sbase + AOF_Q + row * QROWB + c8 * 2,
              Q + (brow + q0 + row) * D_ + headoff + c8);
    }
    // mask as 0/1 half table (8 cols per thread, 256 threads -> 2048 cols)
    {
        int c0 = tid * 8;
        uint32_t hw[4];
#pragma unroll
        for (int j = 0; j < 4; j++) {
            int2 mv = *(const int2*)&mask[b * S_ + c0 + 2 * j];
            uint32_t lo = mv.x ? 0x3C00u : 0u;
            uint32_t hi = mv.y ? 0x3C00u : 0u;
            hw[j] = lo | (hi << 16);
        }
        *(uint4*)(smc + AOF_MH + c0 * 2) = make_uint4(hw[0], hw[1], hw[2], hw[3]);
    }
    issueKV(0);
    cpa_commit();
    issueKV(1);
    cpa_commit();

    const int wm = warp * 16;              // 8 warps x 16 rows (1 m-tile)

    int rowQ = wm + (lane & 15);
    int colQ = (lane >> 4) * 8;
    int rowK = (lane & 7) + (lane >> 4) * 8;
    int colK = ((lane >> 3) & 1) * 8;
    int rowV = (lane & 7) + ((lane >> 3) & 1) * 8;
    int colV = (lane >> 4) * 8;
    uint32_t qBase = sbase + AOF_Q + (rowQ * QP + colQ) * 2;
    uint32_t kOff  = (rowK * QP + colK) * 2;
    uint32_t vOff  = (rowV * QP + colV) * 2;

    float o[8][4];
#pragma unroll
    for (int nt = 0; nt < 8; nt++)
#pragma unroll
        for (int r = 0; r < 4; r++) o[nt][r] = 0.f;
    float ls0 = 0.f, ls1 = 0.f;           // fp32 row-sum accumulators

    for (int i = 0; i < 16; i++) {
        cpa_wait<1>();
        __syncthreads();
        uint32_t kBase = sbase + AOF_K + (i & 1) * AKSZ + kOff;
        uint32_t vBase = sbase + AOF_V + (i & 1) * AKSZ;

        // ---- S = Q K^T, fp16 accumulate (Q carries log2e/8) ----
        uint32_t sch[16][2];
#pragma unroll
        for (int nt = 0; nt < 16; nt++) { sch[nt][0] = 0u; sch[nt][1] = 0u; }

#pragma unroll
        for (int kk = 0; kk < 4; kk++) {
            int kb = kk * 16;
            uint32_t af[4];
            ldsm4(af, qBase + kb * 2);
#pragma unroll
            for (int ntp = 0; ntp < 8; ntp++) {
                uint32_t r[4];
                ldsm4(r, kBase + (ntp * 16 * QP + kb) * 2);
                uint32_t bf0[2] = {r[0], r[1]};
                uint32_t bf1[2] = {r[2], r[3]};
                mma16h(sch[2*ntp],   af, bf0);
                mma16h(sch[2*ntp+1], af, bf1);
            }
        }

        // ---- p = exp2(s) * mask : 32 ex2h2 + 32 hmul2, in place ----
        int colbase = i * 128;
#pragma unroll
        for (int nt = 0; nt < 16; nt++) {
            uint32_t m2 = *(const uint32_t*)(smc + AOF_MH + (colbase + nt * 8 + 2 * t) * 2);
            sch[nt][0] = hmul2u(ex2h2(sch[nt][0]), m2);
            sch[nt][1] = hmul2u(ex2h2(sch[nt][1]), m2);
        }

        // ---- row sums via hadd2 trees (fma/alu pipes; tensor untouched) ----
        {
            uint32_t a0 = hadd2u(sch[0][0], sch[1][0]);
            uint32_t a1 = hadd2u(sch[2][0], sch[3][0]);
            uint32_t a2 = hadd2u(sch[4][0], sch[5][0]);
            uint32_t a3 = hadd2u(sch[6][0], sch[7][0]);
            uint32_t a4 = hadd2u(sch[8][0], sch[9][0]);
            uint32_t a5 = hadd2u(sch[10][0], sch[11][0]);
            uint32_t a6 = hadd2u(sch[12][0], sch[13][0]);
            uint32_t a7 = hadd2u(sch[14][0], sch[15][0]);
            a0 = hadd2u(a0, a1); a2 = hadd2u(a2, a3);
            a4 = hadd2u(a4, a5); a6 = hadd2u(a6, a7);
            a0 = hadd2u(a0, a2); a4 = hadd2u(a4, a6);
            a0 = hadd2u(a0, a4);
            float2 f0 = __half22float2(*(__half2*)&a0);
            ls0 += f0.x + f0.y;

            uint32_t b0 = hadd2u(sch[0][1], sch[1][1]);
            uint32_t b1 = hadd2u(sch[2][1], sch[3][1]);
            uint32_t b2 = hadd2u(sch[4][1], sch[5][1]);
            uint32_t b3 = hadd2u(sch[6][1], sch[7][1]);
            uint32_t b4 = hadd2u(sch[8][1], sch[9][1]);
            uint32_t b5 = hadd2u(sch[10][1], sch[11][1]);
            uint32_t b6 = hadd2u(sch[12][1], sch[13][1]);
            uint32_t b7 = hadd2u(sch[14][1], sch[15][1]);
            b0 = hadd2u(b0, b1); b2 = hadd2u(b2, b3);
            b4 = hadd2u(b4, b5); b6 = hadd2u(b6, b7);
            b0 = hadd2u(b0, b2); b4 = hadd2u(b4, b6);
            b0 = hadd2u(b0, b4);
            float2 f1 = __half22float2(*(__half2*)&b0);
            ls1 += f1.x + f1.y;
        }

        // ---- O += P @ V : P A-frags ARE the sch registers ----
#pragma unroll
        for (int kk = 0; kk < 8; kk++) {
            uint32_t af[4];
            af[0] = sch[2*kk  ][0];
            af[1] = sch[2*kk  ][1];
            af[2] = sch[2*kk+1][0];
            af[3] = sch[2*kk+1][1];
            uint32_t vk = vBase + kk * 16 * QROWB;
#pragma unroll
            for (int ntv = 0; ntv < 4; ntv++) {
                uint32_t r[4];
                ldsm4t(r, vk + vOff + ntv * 16 * 2);
                uint32_t bf0[2] = {r[0], r[1]};
                uint32_t bf1[2] = {r[2], r[3]};
                mma16(o[2*ntv],   af, bf0);
                mma16(o[2*ntv+1], af, bf1);
            }
        }

        __syncthreads();
        if (i + 2 < 16) issueKV(i + 2);
        cpa_commit();
    }

    // ---- epilogue: quad-reduce row sums, normalize, store half2 ----
    ls0 += __shfl_xor_sync(0xffffffffu, ls0, 1);
    ls0 += __shfl_xor_sync(0xffffffffu, ls0, 2);
    ls1 += __shfl_xor_sync(0xffffffffu, ls1, 1);
    ls1 += __shfl_xor_sync(0xffffffffu, ls1, 2);
    float i0 = 1.f / ls0, i1 = 1.f / ls1;
    size_t r0 = brow + q0 + wm + g;
#pragma unroll
    for (int nt = 0; nt < 8; nt++) {
        int c = nt * 8 + 2 * t;
        *(__half2*)(ctx + r0 * D_ + headoff + c) =
            __floats2half2_rn(o[nt][0] * i0, o[nt][1] * i0);
        *(__half2*)(ctx + (r0 + 8) * D_ + headoff + c) =
            __floats2half2_rn(o[nt][2] * i1, o[nt][3] * i1);
    }
}

// ---------------------------------------------------------------------------
// Launch
// ---------------------------------------------------------------------------
extern "C" void kernel_launch(void* const* d_in, const int* in_sizes, int n_in,
                              void* d_out, int out_size) {
    const float* x    = (const float*)d_in[0];
    const int*   mask = (const int*)  d_in[1];
    const float* Wq   = (const float*)d_in[2];
    const float* bq   = (const float*)d_in[3];
    const float* Wk   = (const float*)d_in[4];
    const float* bk   = (const float*)d_in[5];
    const float* Wv   = (const float*)d_in[6];
    const float* bv   = (const float*)d_in[7];
    const float* Wo   = (const float*)d_in[8];
    const float* bo   = (const float*)d_in[9];
    float* out = (float*)d_out;

    __half *xr, *wq, *wk, *wv, *wo, *q, *k, *v, *c;
    cudaGetSymbolAddress((void**)&xr, g_X);
    cudaGetSymbolAddress((void**)&wq, g_Wq);
    cudaGetSymbolAddress((void**)&wk, g_Wk);
    cudaGetSymbolAddress((void**)&wv, g_Wv);
    cudaGetSymbolAddress((void**)&wo, g_Wo);
    cudaGetSymbolAddress((void**)&q,  g_Q);
    cudaGetSymbolAddress((void**)&k,  g_K);
    cudaGetSymbolAddress((void**)&v,  g_V);
    cudaGetSymbolAddress((void**)&c,  g_C);

    cudaFuncSetAttribute(gemm_qkv,
                         cudaFuncAttributeMaxDynamicSharedMemorySize, GEMM_SMEM_BYTES);
    cudaFuncSetAttribute(gemm_o,
                         cudaFuncAttributeMaxDynamicSharedMemorySize, GEMM_SMEM_BYTES);
    cudaFuncSetAttribute(attn_kernel,
                         cudaFuncAttributeMaxDynamicSharedMemorySize, ATTN_SMEM_BYTES);

    // 1) pre-round all operands to fp16 in ONE launch
    //    (y==4 -> x with 8-iter stride; y<4 -> weight matrices)
    int nw4 = D_ * D_ / 4;                // 262144; x chunks = 8 * nw4
    round_all<<<dim3(nw4 / 256, 5), 256>>>(x, Wq, Wk, Wv, Wo,
                                           xr, wq, wk, wv, wo, nw4);

    // 2) fused QKV projections (fp16 out; Q pre-scaled by log2e/8)
    dim3 gqkv(BSZ / 128, D_ / 128, 3);
    gemm_qkv<<<gqkv, 128, GEMM_SMEM_BYTES>>>(xr, wq, wk, wv, bq, bk, bv, q, k, v);

    // 3) attention (128-row CTAs, 256 threads, 2 CTAs/SM)
    attn_kernel<<<dim3(S_ / 128, B_ * H_), ATHREADS, ATTN_SMEM_BYTES>>>(q, k, v, mask, c);

    // 4) output projection (fp32 out)
    dim3 go(BSZ / 128, D_ / 128);
    gemm_o<<<go, 128, GEMM_SMEM_BYTES>>>(c, wo, bo, out);
}